// round 1
// baseline (speedup 1.0000x reference)
#include <cuda_runtime.h>

// out[i] = F[inds[i]] for i in [0, 100)  (CARD=50, output 50x2 = 100 floats)
__global__ void gather_kernel(const float* __restrict__ F,
                              const int* __restrict__ inds,
                              float* __restrict__ out,
                              int n) {
    int i = threadIdx.x;
    if (i < n) {
        out[i] = F[inds[i]];
    }
}

extern "C" void kernel_launch(void* const* d_in, const int* in_sizes, int n_in,
                              void* d_out, int out_size) {
    const float* F    = (const float*)d_in[0];
    const int*   inds = (const int*)d_in[1];
    float*       out  = (float*)d_out;
    int n = in_sizes[1];           // 2*CARD = 100 gathered elements
    gather_kernel<<<1, 128>>>(F, inds, out, n);
}

// round 2
// speedup vs baseline: 1.0769x; 1.0769x over previous
#include <cuda_runtime.h>

// out[i] = F[inds[i]] for i in [0, 100).
// Single warp: thread t handles elements [4t, 4t+4). 25 active lanes.
// LDG.128 index load -> 4 independent gathers (full MLP) -> STG.128.
__global__ void __launch_bounds__(32, 1)
gather_kernel(const float* __restrict__ F,
              const int* __restrict__ inds,
              float* __restrict__ out,
              int n) {
    int t = threadIdx.x;
    int base = t * 4;
    if (base < n) {
        int4 idx = *reinterpret_cast<const int4*>(inds + base);
        float4 v;
        v.x = __ldg(F + idx.x);
        v.y = __ldg(F + idx.y);
        v.z = __ldg(F + idx.z);
        v.w = __ldg(F + idx.w);
        *reinterpret_cast<float4*>(out + base) = v;
    }
}

extern "C" void kernel_launch(void* const* d_in, const int* in_sizes, int n_in,
                              void* d_out, int out_size) {
    const float* F    = (const float*)d_in[0];
    const int*   inds = (const int*)d_in[1];
    float*       out  = (float*)d_out;
    int n = in_sizes[1];   // 100, divisible by 4
    gather_kernel<<<1, 32>>>(F, inds, out, n);
}